// round 2
// baseline (speedup 1.0000x reference)
#include <cuda_runtime.h>
#include <cuda_fp16.h>
#include <stdint.h>

#define BB 4
#define NN 1024
#define EE 32

// Scratch (no allocations allowed): transposed y, norms, CTA partials.
__device__ float g_yT[BB][EE][NN];
__device__ float g_nrm[BB][NN];
__device__ float g_part[128];

// ---------------------------------------------------------------------------
// Kernel 1: y = embedding with coords folded into dims 0,1; store e-major + norms
// ---------------------------------------------------------------------------
__global__ void prep_kernel(const float* __restrict__ emb,
                            const float* __restrict__ coords) {
    int b = blockIdx.y;
    int j = blockIdx.x * blockDim.x + threadIdx.x;   // 0..1023
    const float* ep = emb + ((size_t)(b * NN + j)) * EE;
    float v[EE];
#pragma unroll
    for (int k = 0; k < EE; k += 4) {
        float4 t = *reinterpret_cast<const float4*>(ep + k);
        v[k] = t.x; v[k + 1] = t.y; v[k + 2] = t.z; v[k + 3] = t.w;
    }
    float2 c2 = *reinterpret_cast<const float2*>(coords + ((size_t)(b * NN + j)) * 2);
    v[0] += c2.x;
    v[1] += c2.y;
    float n = 0.f;
#pragma unroll
    for (int k = 0; k < EE; k++) n += v[k] * v[k];
    g_nrm[b][j] = n;
#pragma unroll
    for (int k = 0; k < EE; k++) g_yT[b][k][j] = v[k];   // coalesced in j per e
}

// ---------------------------------------------------------------------------
// Kernel 2: fused sim + row-logsumexp + masked softplus sum.
// grid (32 i-tiles, 4 batches) x 256 threads. Each CTA: rows [i0, i0+32) x all j.
// smem: yT (e-major, 128KB) + norms (4KB) + fp16 sim stash (64KB, sign=mask bit).
// ---------------------------------------------------------------------------
__global__ void __launch_bounds__(256, 1)
main_kernel(const int* __restrict__ mask) {
    extern __shared__ char smem[];
    float*  sYT  = reinterpret_cast<float*>(smem);           // [32][1024]
    float*  sN   = sYT + EE * NN;                            // [1024]
    __half* sSim = reinterpret_cast<__half*>(sN + NN);       // [32][1024]
    float*  sRed = reinterpret_cast<float*>(sSim + 32 * NN); // [8]

    const int tid  = threadIdx.x;
    const int b    = blockIdx.y;
    const int i0   = blockIdx.x * 32;
    const int warp = tid >> 5;
    const int lane = tid & 31;

    // Cooperative load of the whole batch's yT + norms
    {
        const float4* gy4 = reinterpret_cast<const float4*>(&g_yT[b][0][0]);
        float4* sYT4w = reinterpret_cast<float4*>(sYT);
#pragma unroll
        for (int it = 0; it < 32; ++it) {
            int idx = it * 256 + tid;                 // 8192 float4
            sYT4w[idx] = gy4[idx];
        }
        reinterpret_cast<float4*>(sN)[tid] =
            reinterpret_cast<const float4*>(&g_nrm[b][0])[tid];   // 256 float4
    }
    __syncthreads();

    const float4* sYT4 = reinterpret_cast<const float4*>(sYT);
    const float4* sN4  = reinterpret_cast<const float4*>(sN);
    const size_t mrowbase = ((size_t)b * NN + (size_t)(i0 + warp * 4)) * NN;

    float Sneg[4] = {0.f, 0.f, 0.f, 0.f};

    // -------- Pass 1: Gram tile + sim + S_neg + fp16 stash (sign = mask) -----
    for (int jc = 0; jc < 8; ++jc) {
        float acc[4][4];
#pragma unroll
        for (int r = 0; r < 4; r++)
#pragma unroll
            for (int c = 0; c < 4; c++) acc[r][c] = 0.f;

#pragma unroll
        for (int e = 0; e < EE; e++) {
            const float4* row = sYT4 + e * (NN / 4);
            float4 a  = row[(i0 >> 2) + warp];       // broadcast across lanes
            float4 bb = row[jc * 32 + lane];         // lane-consecutive, no conflicts
            acc[0][0] += a.x * bb.x; acc[0][1] += a.x * bb.y; acc[0][2] += a.x * bb.z; acc[0][3] += a.x * bb.w;
            acc[1][0] += a.y * bb.x; acc[1][1] += a.y * bb.y; acc[1][2] += a.y * bb.z; acc[1][3] += a.y * bb.w;
            acc[2][0] += a.z * bb.x; acc[2][1] += a.z * bb.y; acc[2][2] += a.z * bb.z; acc[2][3] += a.z * bb.w;
            acc[3][0] += a.w * bb.x; acc[3][1] += a.w * bb.y; acc[3][2] += a.w * bb.z; acc[3][3] += a.w * bb.w;
        }

        const int jb = jc * 128 + lane * 4;
        float4 njv = sN4[jb >> 2];
        float nj[4] = {njv.x, njv.y, njv.z, njv.w};

#pragma unroll
        for (int r = 0; r < 4; r++) {
            const int i  = i0 + warp * 4 + r;
            const int li = warp * 4 + r;
            const float ni = sN[i];
            // mask is int32 (bool widened): 16B vector load of 4 elements
            int4 m4 = *reinterpret_cast<const int4*>(mask + mrowbase + (size_t)r * NN + jb);
            int mm[4] = {m4.x, m4.y, m4.z, m4.w};
            unsigned short hs[4];
#pragma unroll
            for (int c = 0; c < 4; c++) {
                float ssq  = fmaxf(ni + nj[c] - 2.f * acc[r][c], 0.f);
                float dist = (ssq > 0.f) ? ssq * rsqrtf(ssq) : 0.f;
                float sim  = 1.f / (1.f + __expf(dist - 5.f));   // = sigmoid(5-dist)
                int   j    = jb + c;
                if (!mm[c] && j != i) Sneg[r] += __expf(sim);
                unsigned short h = __half_as_ushort(__float2half(sim));
                hs[c] = h | (mm[c] ? 0x8000u : 0u);   // sign bit carries the mask
            }
            uint2 pk;
            pk.x = (uint32_t)hs[0] | ((uint32_t)hs[1] << 16);
            pk.y = (uint32_t)hs[2] | ((uint32_t)hs[3] << 16);
            *reinterpret_cast<uint2*>(reinterpret_cast<char*>(sSim) +
                                      ((size_t)li * NN + jb) * 2) = pk;  // STS.64
        }
    }

    // Row logsumexp: reduce S_neg across the warp (each warp owns its 4 rows)
    float L[4];
#pragma unroll
    for (int r = 0; r < 4; r++) {
        float s = Sneg[r];
#pragma unroll
        for (int o = 16; o > 0; o >>= 1) s += __shfl_down_sync(0xffffffffu, s, o);
        s = __shfl_sync(0xffffffffu, s, 0);
        L[r] = __logf(s);
    }

    // -------- Pass 2: masked softplus over stashed sims (no global loads;
    // each warp only reads the rows it wrote -> no sync needed) ---------------
    float csum = 0.f;
    for (int jc = 0; jc < 8; ++jc) {
        const int jb = jc * 128 + lane * 4;
#pragma unroll
        for (int r = 0; r < 4; r++) {
            const int li = warp * 4 + r;
            uint2 pk = *reinterpret_cast<const uint2*>(reinterpret_cast<const char*>(sSim) +
                                                       ((size_t)li * NN + jb) * 2);
            unsigned short hw[4];
            hw[0] = (unsigned short)(pk.x & 0xffffu);
            hw[1] = (unsigned short)(pk.x >> 16);
            hw[2] = (unsigned short)(pk.y & 0xffffu);
            hw[3] = (unsigned short)(pk.y >> 16);
#pragma unroll
            for (int c = 0; c < 4; c++) {
                if (hw[c] & 0x8000u) {   // mask bit set -> positive pair
                    float sv = __half2float(__ushort_as_half(
                                   (unsigned short)(hw[c] & 0x7fffu)));
                    csum += __logf(1.f + __expf(L[r] - sv));
                }
            }
        }
    }
#pragma unroll
    for (int o = 16; o > 0; o >>= 1) csum += __shfl_down_sync(0xffffffffu, csum, o);
    if (lane == 0) sRed[warp] = csum;
    __syncthreads();
    if (tid == 0) {
        float t = 0.f;
#pragma unroll
        for (int w = 0; w < 8; w++) t += sRed[w];
        g_part[b * 32 + blockIdx.x] = t;
    }
}

// ---------------------------------------------------------------------------
// Kernel 3: deterministic fixed-order tree reduction of 128 CTA partials
// ---------------------------------------------------------------------------
__global__ void reduce_kernel(float* __restrict__ out) {
    __shared__ double sh[128];
    int t = threadIdx.x;
    sh[t] = (double)g_part[t];
    __syncthreads();
#pragma unroll
    for (int s = 64; s > 0; s >>= 1) {
        if (t < s) sh[t] += sh[t + s];
        __syncthreads();
    }
    if (t == 0) out[0] = (float)sh[0];
}

// ---------------------------------------------------------------------------
extern "C" void kernel_launch(void* const* d_in, const int* in_sizes, int n_in,
                              void* d_out, int out_size) {
    (void)in_sizes; (void)n_in; (void)out_size;
    const float* emb    = (const float*)d_in[0];   // [4,1024,32]
    const float* coords = (const float*)d_in[1];   // [4,1024,2]
    const int*   mask   = (const int*)d_in[2];     // [4,1024,1024] bool->int32
    float* out          = (float*)d_out;           // scalar

    prep_kernel<<<dim3(4, 4), 256>>>(emb, coords);

    size_t smem = (size_t)EE * NN * sizeof(float)     // yT     131072
                + (size_t)NN * sizeof(float)          // norms    4096
                + (size_t)32 * NN * sizeof(__half)    // sim     65536
                + 64;                                 // reduction slots
    cudaFuncSetAttribute(main_kernel, cudaFuncAttributeMaxDynamicSharedMemorySize,
                         (int)smem);
    main_kernel<<<dim3(32, 4), 256, smem>>>(mask);

    reduce_kernel<<<1, 128>>>(out);
}

// round 3
// speedup vs baseline: 1.6384x; 1.6384x over previous
#include <cuda_runtime.h>
#include <stdint.h>

#define NN 1024
#define EE 32

// Scratch (no allocations allowed)
__device__ float g_part[128];
__device__ unsigned int g_done = 0;

// ---------------------------------------------------------------------------
// Single fused kernel.
// grid (32 i-tiles, 4 batches) x 256 threads. Each CTA: rows [i0,i0+32) x all j.
// smem: yT (e-major, 128KB) + norms (4KB) + 8 warp-reduction slots.
// Phase A: build yT/norms from emb+coords (emb L2-resident across CTAs).
// Phase B: 4x4 register-tile Gram + fused sim/accumulator epilogue (one pass).
// Phase C: row closed-form via log1p Taylor; CTA partial; last CTA reduces.
// ---------------------------------------------------------------------------
__global__ void __launch_bounds__(256, 1)
fused_kernel(const float* __restrict__ emb,
             const float* __restrict__ coords,
             const int*   __restrict__ mask,
             float*       __restrict__ out) {
    extern __shared__ char smem[];
    float* sYT  = reinterpret_cast<float*>(smem);   // [32][1024]
    float* sN   = sYT + EE * NN;                    // [1024]
    float* sRed = sN + NN;                          // [8]
    __shared__ int sIsLast;

    const int tid  = threadIdx.x;
    const int b    = blockIdx.y;
    const int i0   = blockIdx.x * 32;
    const int warp = tid >> 5;
    const int lane = tid & 31;

    // ---------------- Phase A: inline prep (4 rows per thread) --------------
#pragma unroll
    for (int k = 0; k < 4; k++) {
        const int j = tid + k * 256;
        const float* ep = emb + ((size_t)(b * NN + j)) * EE;
        float v[EE];
#pragma unroll
        for (int e = 0; e < EE; e += 4) {
            float4 t = *reinterpret_cast<const float4*>(ep + e);
            v[e] = t.x; v[e + 1] = t.y; v[e + 2] = t.z; v[e + 3] = t.w;
        }
        float2 c2 = *reinterpret_cast<const float2*>(coords + ((size_t)(b * NN + j)) * 2);
        v[0] += c2.x;
        v[1] += c2.y;
        float n = 0.f;
#pragma unroll
        for (int e = 0; e < EE; e++) {
            sYT[e * NN + j] = v[e];        // lanes j-consecutive: conflict-free
            n += v[e] * v[e];
        }
        sN[j] = n;
    }
    __syncthreads();

    // ---------------- Phase B: Gram tile + fused epilogue -------------------
    const float4* sYT4 = reinterpret_cast<const float4*>(sYT);
    const float4* sN4  = reinterpret_cast<const float4*>(sN);
    const size_t mrowbase = ((size_t)b * NN + (size_t)(i0 + warp * 4)) * NN;

    // Per-row accumulators: S (neg exp-sum), A=Σpos e, B=Σpos e², P=Σpos sim, C=count
    float Sr[4] = {0, 0, 0, 0}, Ar[4] = {0, 0, 0, 0}, Br[4] = {0, 0, 0, 0};
    float Pr[4] = {0, 0, 0, 0}, Cr[4] = {0, 0, 0, 0};

    float nis[4];
#pragma unroll
    for (int r = 0; r < 4; r++) nis[r] = sN[i0 + warp * 4 + r];

    for (int jc = 0; jc < 8; ++jc) {
        float acc[4][4];
#pragma unroll
        for (int r = 0; r < 4; r++)
#pragma unroll
            for (int c = 0; c < 4; c++) acc[r][c] = 0.f;

#pragma unroll
        for (int e = 0; e < EE; e++) {
            const float4* row = sYT4 + e * (NN / 4);
            float4 a  = row[(i0 >> 2) + warp];     // broadcast across lanes
            float4 bb = row[jc * 32 + lane];       // lane-consecutive
            acc[0][0] += a.x * bb.x; acc[0][1] += a.x * bb.y; acc[0][2] += a.x * bb.z; acc[0][3] += a.x * bb.w;
            acc[1][0] += a.y * bb.x; acc[1][1] += a.y * bb.y; acc[1][2] += a.y * bb.z; acc[1][3] += a.y * bb.w;
            acc[2][0] += a.z * bb.x; acc[2][1] += a.z * bb.y; acc[2][2] += a.z * bb.z; acc[2][3] += a.z * bb.w;
            acc[3][0] += a.w * bb.x; acc[3][1] += a.w * bb.y; acc[3][2] += a.w * bb.z; acc[3][3] += a.w * bb.w;
        }

        const int jb = jc * 128 + lane * 4;
        float4 njv = sN4[jb >> 2];
        float nj[4] = {njv.x, njv.y, njv.z, njv.w};

#pragma unroll
        for (int r = 0; r < 4; r++) {
            const int i = i0 + warp * 4 + r;
            const float ni = nis[r];
            int4 m4 = *reinterpret_cast<const int4*>(mask + mrowbase + (size_t)r * NN + jb);
            int mm[4] = {m4.x, m4.y, m4.z, m4.w};
#pragma unroll
            for (int c = 0; c < 4; c++) {
                float ssq  = fmaxf(ni + nj[c] - 2.f * acc[r][c], 0.f);
                float dist = (ssq > 0.f) ? ssq * rsqrtf(ssq) : 0.f;
                float t    = __expf(dist - 5.f);
                float sim  = __fdividef(1.f, 1.f + t);     // sigmoid(5-dist)
                float ex   = __expf(sim);
                bool  pos  = (mm[c] != 0);
                bool  neg  = !pos && ((jb + c) != i);
                Sr[r] += neg ? ex : 0.f;
                Ar[r] += pos ? ex : 0.f;
                Br[r] += pos ? ex * ex : 0.f;
                Pr[r] += pos ? sim : 0.f;
                Cr[r] += pos ? 1.f : 0.f;
            }
        }
    }

    // ---------------- Phase C: row closed form + reductions -----------------
    float csum = 0.f;
#pragma unroll
    for (int r = 0; r < 4; r++) {
        float s = Sr[r], a = Ar[r], bq = Br[r], p = Pr[r], cn = Cr[r];
#pragma unroll
        for (int o = 16; o > 0; o >>= 1) {
            s  += __shfl_down_sync(0xffffffffu, s,  o);
            a  += __shfl_down_sync(0xffffffffu, a,  o);
            bq += __shfl_down_sync(0xffffffffu, bq, o);
            p  += __shfl_down_sync(0xffffffffu, p,  o);
            cn += __shfl_down_sync(0xffffffffu, cn, o);
        }
        if (lane == 0) {
            float L  = __logf(s);
            float rS = __fdividef(1.f, s);
            // Σ_pos [L - sim + log1p(e^sim / S)], log1p to 2nd order
            csum += cn * L - p + a * rS - 0.5f * bq * rS * rS;
        }
    }
    if (lane == 0) sRed[warp] = csum;
    __syncthreads();

    if (tid == 0) {
        float tsum = 0.f;
#pragma unroll
        for (int w = 0; w < 8; w++) tsum += sRed[w];
        g_part[b * 32 + blockIdx.x] = tsum;
        __threadfence();
        unsigned v = atomicAdd(&g_done, 1u);
        sIsLast = (v == 127u);
    }
    __syncthreads();

    // Last CTA: deterministic fixed-order tree over the 128 partials
    if (sIsLast) {
        double* dsh = reinterpret_cast<double*>(sYT);   // reuse smem
        if (tid < 128) dsh[tid] = (double)g_part[tid];
        __syncthreads();
#pragma unroll
        for (int s = 64; s > 0; s >>= 1) {
            if (tid < s) dsh[tid] += dsh[tid + s];
            __syncthreads();
        }
        if (tid == 0) {
            out[0] = (float)dsh[0];
            g_done = 0;                 // reset for next replay
        }
    }
}

// ---------------------------------------------------------------------------
extern "C" void kernel_launch(void* const* d_in, const int* in_sizes, int n_in,
                              void* d_out, int out_size) {
    (void)in_sizes; (void)n_in; (void)out_size;
    const float* emb    = (const float*)d_in[0];   // [4,1024,32]
    const float* coords = (const float*)d_in[1];   // [4,1024,2]
    const int*   mask   = (const int*)d_in[2];     // [4,1024,1024] bool->int32
    float* out          = (float*)d_out;           // scalar

    size_t smem = (size_t)EE * NN * sizeof(float)   // yT    131072
                + (size_t)NN * sizeof(float)        // norms   4096
                + 64;                               // reduction slots
    cudaFuncSetAttribute(fused_kernel, cudaFuncAttributeMaxDynamicSharedMemorySize,
                         (int)smem);
    fused_kernel<<<dim3(32, 4), 256, smem>>>(emb, coords, mask, out);
}